// round 2
// baseline (speedup 1.0000x reference)
#include <cuda_runtime.h>
#include <cstdint>
#include <math.h>

// Problem dims
#define N_B   32
#define T_B   243
#define V_B   17
#define D_B   512
#define DM_B  384
#define DA_B  128
#define H_B   4
#define HD_B  32
#define NT_B  (N_B * T_B)          // 7776
#define MROWS (NT_B * V_B)         // 132192

// ---------------- scratch (static device memory; no allocations) ----------
__device__ float g_xc  [67682304];   // MROWS * 512  (concat of xm_out | xa_out)
__device__ float g_qkv [50761728];   // MROWS * 384
__device__ float g_o   [16920576];   // MROWS * 128
__device__ float g_h   [135364608];  // MROWS * 1024 (MLP hidden)
__device__ float g_rrms_a[132192];
__device__ float g_rrms_f[132192];

// ---------------- helpers -------------------------------------------------
__device__ __forceinline__ float to_tf32(float v) {
    uint32_t u;
    asm("cvt.rna.tf32.f32 %0, %1;" : "=r"(u) : "f"(v));
    return __uint_as_float(u);
}

__device__ __forceinline__ void mma8(float d[4], const uint32_t a[4], const uint32_t b[2]) {
    asm volatile(
        "mma.sync.aligned.m16n8k8.row.col.f32.tf32.tf32.f32 "
        "{%0,%1,%2,%3},{%4,%5,%6,%7},{%8,%9},{%0,%1,%2,%3};"
        : "+f"(d[0]), "+f"(d[1]), "+f"(d[2]), "+f"(d[3])
        : "r"(a[0]), "r"(a[1]), "r"(a[2]), "r"(a[3]), "r"(b[0]), "r"(b[1]));
}

__device__ __forceinline__ float gelu_f(float v) {
    return 0.5f * v * (1.0f + erff(v * 0.7071067811865475f));
}

// ---------------- generic tf32 GEMM:  out = act(A * W^T + bias) -----------
// A: M x K (row stride lda, element offset aoff), optionally scaled by
//    rowscale[m] * colscale[k] (fused RMSNorm).
// W: N x K row-major. N (grid.x*128) always divisible by 128. K % 32 == 0.
// MODE: 0 = bias, 1 = bias+gelu, 2 = bias+residual(x, stride 512)
template <int MODE>
__device__ __forceinline__ void gemm_core(
    const float* __restrict__ A, int lda, int aoff,
    const float* __restrict__ W, int K,
    const float* __restrict__ bias,
    const float* __restrict__ rowscale,
    const float* __restrict__ colscale,
    const float* __restrict__ residual,
    float* __restrict__ out, int ldc, int coff,
    int M)
{
    __shared__ float As[128][36];
    __shared__ float Bs[128][36];

    const int tid  = threadIdx.x;
    const int lane = tid & 31;
    const int warp = tid >> 5;
    const int wm   = (warp & 1) * 64;   // 2 warps along M
    const int wn   = (warp >> 1) * 32;  // 4 warps along N
    const int n0   = blockIdx.x * 128;  // N-tiles fastest -> A-tile L2 reuse
    const int m0   = blockIdx.y * 128;

    const int sr = tid >> 3;        // 0..31 staging row
    const int sc = (tid & 7) * 4;   // 0..28 staging col (float4)

    float acc[4][4][4];
#pragma unroll
    for (int i = 0; i < 4; i++)
#pragma unroll
        for (int j = 0; j < 4; j++)
#pragma unroll
            for (int q = 0; q < 4; q++) acc[i][j][q] = 0.f;

    for (int kk = 0; kk < K; kk += 32) {
        float4 av[4], bv[4];
#pragma unroll
        for (int i = 0; i < 4; i++) {
            int row = sr + i * 32;
            int gm  = m0 + row;
            float4 v = make_float4(0.f, 0.f, 0.f, 0.f);
            if (gm < M) {
                v = *(const float4*)(A + (size_t)gm * lda + aoff + kk + sc);
                if (rowscale) {
                    float s = rowscale[gm];
                    v.x *= s; v.y *= s; v.z *= s; v.w *= s;
                }
                if (colscale) {
                    float4 w = *(const float4*)(colscale + kk + sc);
                    v.x *= w.x; v.y *= w.y; v.z *= w.z; v.w *= w.w;
                }
            }
            av[i] = v;
            bv[i] = *(const float4*)(W + (size_t)(n0 + row) * K + kk + sc);
        }
        __syncthreads();   // previous iteration's compute done
#pragma unroll
        for (int i = 0; i < 4; i++) {
            int row = sr + i * 32;
            As[row][sc + 0] = to_tf32(av[i].x);
            As[row][sc + 1] = to_tf32(av[i].y);
            As[row][sc + 2] = to_tf32(av[i].z);
            As[row][sc + 3] = to_tf32(av[i].w);
            Bs[row][sc + 0] = to_tf32(bv[i].x);
            Bs[row][sc + 1] = to_tf32(bv[i].y);
            Bs[row][sc + 2] = to_tf32(bv[i].z);
            Bs[row][sc + 3] = to_tf32(bv[i].w);
        }
        __syncthreads();

        const int fr = lane >> 2;
        const int fc = lane & 3;
#pragma unroll
        for (int ks = 0; ks < 4; ks++) {
            const int k0 = ks * 8;
            uint32_t af[4][4], bf[4][2];
#pragma unroll
            for (int mt = 0; mt < 4; mt++) {
                int am = wm + mt * 16;
                af[mt][0] = __float_as_uint(As[am + fr][k0 + fc]);
                af[mt][1] = __float_as_uint(As[am + fr + 8][k0 + fc]);
                af[mt][2] = __float_as_uint(As[am + fr][k0 + fc + 4]);
                af[mt][3] = __float_as_uint(As[am + fr + 8][k0 + fc + 4]);
            }
#pragma unroll
            for (int nt = 0; nt < 4; nt++) {
                int bn = wn + nt * 8;
                bf[nt][0] = __float_as_uint(Bs[bn + fr][k0 + fc]);
                bf[nt][1] = __float_as_uint(Bs[bn + fr][k0 + fc + 4]);
            }
#pragma unroll
            for (int mt = 0; mt < 4; mt++)
#pragma unroll
                for (int nt = 0; nt < 4; nt++)
                    mma8(acc[mt][nt], af[mt], bf[nt]);
        }
    }

    // epilogue
    const int er = lane >> 2;
    const int ec = (lane & 3) * 2;
#pragma unroll
    for (int mt = 0; mt < 4; mt++) {
        int row0 = m0 + wm + mt * 16 + er;
#pragma unroll
        for (int nt = 0; nt < 4; nt++) {
            int col = n0 + wn + nt * 8 + ec;
#pragma unroll
            for (int half = 0; half < 2; half++) {
                int row = row0 + half * 8;
                if (row < M) {
#pragma unroll
                    for (int j = 0; j < 2; j++) {
                        float v = acc[mt][nt][half * 2 + j] + bias[col + j];
                        if (MODE == 1) v = gelu_f(v);
                        if (MODE == 2) v += residual[(size_t)row * 512 + col + j];
                        out[(size_t)row * ldc + coff + col + j] = v;
                    }
                }
            }
        }
    }
}

// ---------------- GEMM wrappers ------------------------------------------
__global__ __launch_bounds__(256, 1) void k_gemm_qkv(
    const float* __restrict__ x, const float* __restrict__ in_w,
    const float* __restrict__ in_b, const float* __restrict__ na_w)
{
    gemm_core<0>(x, 512, 384, in_w, 128, in_b, g_rrms_a, na_w, nullptr,
                 g_qkv, 384, 0, MROWS);
}

__global__ __launch_bounds__(256, 1) void k_gemm_proj(
    const float* __restrict__ out_w, const float* __restrict__ out_b)
{
    gemm_core<0>(g_o, 128, 0, out_w, 128, out_b, nullptr, nullptr, nullptr,
                 g_xc, 512, 384, MROWS);
}

__global__ __launch_bounds__(256, 1) void k_gemm_mlp1(
    const float* __restrict__ cm_w1, const float* __restrict__ cm_b1,
    const float* __restrict__ nf_w)
{
    gemm_core<1>(g_xc, 512, 0, cm_w1, 512, cm_b1, g_rrms_f, nf_w, nullptr,
                 g_h, 1024, 0, MROWS);
}

__global__ __launch_bounds__(256, 1) void k_gemm_mlp2(
    const float* __restrict__ cm_w2, const float* __restrict__ cm_b2,
    const float* __restrict__ x, float* __restrict__ out)
{
    gemm_core<2>(g_h, 1024, 0, cm_w2, 1024, cm_b2, nullptr, nullptr, x,
                 out, 512, 0, MROWS);
}

// ---------------- token mixer (mix over V=17, per channel d<384) ---------
__global__ __launch_bounds__(384) void k_tokenmix(
    const float* __restrict__ x,
    const float* __restrict__ w1, const float* __restrict__ b1,
    const float* __restrict__ w2, const float* __restrict__ b2)
{
    __shared__ float sw1[289], sw2[289], sb1[17], sb2[17];
    int tid = threadIdx.x;
    if (tid < 289) { sw1[tid] = w1[tid]; sw2[tid] = w2[tid]; }
    if (tid < 17)  { sb1[tid] = b1[tid]; sb2[tid] = b2[tid]; }
    __syncthreads();

    size_t base = (size_t)blockIdx.x * V_B * 512;
    int d = tid;  // 0..383
    float xv[17];
#pragma unroll
    for (int v = 0; v < 17; v++) xv[v] = x[base + (size_t)v * 512 + d];
    float h[17];
#pragma unroll
    for (int u = 0; u < 17; u++) {
        float s = sb1[u];
#pragma unroll
        for (int v = 0; v < 17; v++) s += sw1[u * 17 + v] * xv[v];
        h[u] = gelu_f(s);
    }
#pragma unroll
    for (int u = 0; u < 17; u++) {
        float s = sb2[u];
#pragma unroll
        for (int v = 0; v < 17; v++) s += sw2[u * 17 + v] * h[v];
        g_xc[base + (size_t)u * 512 + d] = s;
    }
}

// ---------------- per-row inverse RMS ------------------------------------
__device__ __forceinline__ void rowrms_core(
    const float* __restrict__ src, int stride, int off, int ncols,
    float invn, float* __restrict__ out)
{
    int row = blockIdx.x * (blockDim.x >> 5) + (threadIdx.x >> 5);
    if (row >= MROWS) return;
    int lane = threadIdx.x & 31;
    const float* p = src + (size_t)row * stride + off;
    float ss = 0.f;
    for (int i = lane * 4; i < ncols; i += 128) {
        float4 v = *(const float4*)(p + i);
        ss += v.x * v.x + v.y * v.y + v.z * v.z + v.w * v.w;
    }
#pragma unroll
    for (int s = 16; s; s >>= 1) ss += __shfl_xor_sync(0xffffffffu, ss, s);
    if (lane == 0) out[row] = rsqrtf(ss * invn + 1e-6f);
}

__global__ __launch_bounds__(256) void k_rowrms_a(const float* __restrict__ x) {
    rowrms_core(x, 512, 384, 128, 1.0f / 128.0f, g_rrms_a);
}
__global__ __launch_bounds__(256) void k_rowrms_f() {
    rowrms_core(g_xc, 512, 0, 512, 1.0f / 512.0f, g_rrms_f);
}

// ---------------- attention (one block per (n,t); 17x17 per head) --------
__global__ __launch_bounds__(128) void k_attn() {
    __shared__ __align__(16) float s[17 * 384];
    int b = blockIdx.x;
    const float4* g4 = (const float4*)(g_qkv + (size_t)b * 17 * 384);
    float4* s4 = (float4*)s;
    for (int i = threadIdx.x; i < 17 * 96; i += 128) s4[i] = g4[i];
    __syncthreads();

    int tid = threadIdx.x;
    if (tid < 68) {
        int q  = tid % 17;
        int hh = tid / 17;
        float qv[32];
#pragma unroll
        for (int i = 0; i < 8; i++) {
            float4 v = *(const float4*)&s[q * 384 + hh * 32 + i * 4];
            qv[i * 4] = v.x; qv[i * 4 + 1] = v.y; qv[i * 4 + 2] = v.z; qv[i * 4 + 3] = v.w;
        }
        float sc[17];
        float mx = -1e30f;
#pragma unroll
        for (int j = 0; j < 17; j++) {
            const float* kp = &s[j * 384 + 128 + hh * 32];
            float a = 0.f;
#pragma unroll
            for (int i = 0; i < 8; i++) {
                float4 v = *(const float4*)(kp + i * 4);
                a += qv[i * 4] * v.x + qv[i * 4 + 1] * v.y +
                     qv[i * 4 + 2] * v.z + qv[i * 4 + 3] * v.w;
            }
            a *= 0.17677669529663687f;  // 1/sqrt(32)
            sc[j] = a;
            mx = fmaxf(mx, a);
        }
        float sum = 0.f;
#pragma unroll
        for (int j = 0; j < 17; j++) { sc[j] = expf(sc[j] - mx); sum += sc[j]; }
        float inv = 1.f / sum;
        float ov[32];
#pragma unroll
        for (int i = 0; i < 32; i++) ov[i] = 0.f;
#pragma unroll
        for (int j = 0; j < 17; j++) {
            float p = sc[j] * inv;
            const float* vp = &s[j * 384 + 256 + hh * 32];
#pragma unroll
            for (int i = 0; i < 8; i++) {
                float4 v = *(const float4*)(vp + i * 4);
                ov[i * 4]     += p * v.x;
                ov[i * 4 + 1] += p * v.y;
                ov[i * 4 + 2] += p * v.z;
                ov[i * 4 + 3] += p * v.w;
            }
        }
        float* op = g_o + ((size_t)b * 17 + q) * 128 + hh * 32;
#pragma unroll
        for (int i = 0; i < 8; i++)
            *(float4*)(op + i * 4) =
                make_float4(ov[i * 4], ov[i * 4 + 1], ov[i * 4 + 2], ov[i * 4 + 3]);
    }
}

// ---------------- launch --------------------------------------------------
extern "C" void kernel_launch(void* const* d_in, const int* in_sizes, int n_in,
                              void* d_out, int out_size)
{
    const float* x     = (const float*)d_in[0];
    const float* tm_w1 = (const float*)d_in[1];
    const float* tm_b1 = (const float*)d_in[2];
    const float* tm_w2 = (const float*)d_in[3];
    const float* tm_b2 = (const float*)d_in[4];
    const float* na_w  = (const float*)d_in[5];
    const float* in_w  = (const float*)d_in[6];
    const float* in_b  = (const float*)d_in[7];
    const float* out_w = (const float*)d_in[8];
    const float* out_b = (const float*)d_in[9];
    const float* nf_w  = (const float*)d_in[10];
    const float* cm_w1 = (const float*)d_in[11];
    const float* cm_b1 = (const float*)d_in[12];
    const float* cm_w2 = (const float*)d_in[13];
    const float* cm_b2 = (const float*)d_in[14];
    float* out = (float*)d_out;

    const int mt = (MROWS + 127) / 128;  // 1033 M-tiles

    k_tokenmix<<<NT_B, 384>>>(x, tm_w1, tm_b1, tm_w2, tm_b2);
    k_rowrms_a<<<MROWS / 8, 256>>>(x);
    k_gemm_qkv<<<dim3(3, mt), 256>>>(x, in_w, in_b, na_w);
    k_attn<<<NT_B, 128>>>();
    k_gemm_proj<<<dim3(1, mt), 256>>>(out_w, out_b);
    k_rowrms_f<<<MROWS / 8, 256>>>();
    k_gemm_mlp1<<<dim3(8, mt), 256>>>(cm_w1, cm_b1, nf_w);
    k_gemm_mlp2<<<dim3(4, mt), 256>>>(cm_w2, cm_b2, x, out);
}

// round 3
// speedup vs baseline: 1.5071x; 1.5071x over previous
#include <cuda_runtime.h>
#include <cuda_fp16.h>
#include <cstdint>
#include <math.h>

// Problem dims
#define N_B   32
#define T_B   243
#define V_B   17
#define NT_B  (N_B * T_B)          // 7776
#define MROWS (NT_B * V_B)         // 132192

// ---------------- scratch (static device memory; no allocations) ----------
__device__ __half g_xc [67682304];   // MROWS * 512  (concat xm_out | xa_out), fp16
__device__ float  g_qkv[50761728];   // MROWS * 384  (fp32 for attention accuracy)
__device__ float  g_o  [16920576];   // MROWS * 128
__device__ __half g_h  [135364608];  // MROWS * 1024 (MLP hidden), fp16
__device__ float  g_rrms_a[132192];
__device__ float  g_rrms_f[132192];

// ---------------- helpers -------------------------------------------------
__device__ __forceinline__ float gelu_f(float v) {
    return 0.5f * v * (1.0f + erff(v * 0.7071067811865475f));
}

__device__ __forceinline__ uint32_t smaddr(const void* p) {
    return (uint32_t)__cvta_generic_to_shared(p);
}

__device__ __forceinline__ void ldsm4(uint32_t* r, uint32_t a) {
    asm volatile("ldmatrix.sync.aligned.m8n8.x4.shared.b16 {%0,%1,%2,%3}, [%4];"
        : "=r"(r[0]), "=r"(r[1]), "=r"(r[2]), "=r"(r[3]) : "r"(a));
}
__device__ __forceinline__ void ldsm2(uint32_t* r, uint32_t a) {
    asm volatile("ldmatrix.sync.aligned.m8n8.x2.shared.b16 {%0,%1}, [%2];"
        : "=r"(r[0]), "=r"(r[1]) : "r"(a));
}
__device__ __forceinline__ void hmma(float* d, const uint32_t* a, const uint32_t* b) {
    asm volatile(
        "mma.sync.aligned.m16n8k16.row.col.f32.f16.f16.f32 "
        "{%0,%1,%2,%3},{%4,%5,%6,%7},{%8,%9},{%0,%1,%2,%3};"
        : "+f"(d[0]), "+f"(d[1]), "+f"(d[2]), "+f"(d[3])
        : "r"(a[0]), "r"(a[1]), "r"(a[2]), "r"(a[3]), "r"(b[0]), "r"(b[1]));
}

// ---------------- fp16 tensor-core GEMM: out = act(A * W^T + bias) --------
// 128x128x32 tile, 256 threads (8 warps, 64x32 warp tiles), double-buffered
// smem with 40-half pitch (conflict-free ldmatrix), register prefetch.
// MODE: 0 = bias, 1 = bias+gelu, 2 = bias+residual(fp32, stride 512)
#define SLD 40

template <int MODE, typename AT, typename OT>
__device__ __forceinline__ void gemm_core(
    const AT* __restrict__ A, int lda, int aoff,
    const float* __restrict__ W, int K,
    const float* __restrict__ bias,
    const float* __restrict__ rowscale,
    const float* __restrict__ colscale,
    const float* __restrict__ residual,
    OT* __restrict__ out, int ldc, int coff,
    int M)
{
    __shared__ __half As[2][128 * SLD];
    __shared__ __half Bs[2][128 * SLD];

    const int tid  = threadIdx.x;
    const int lane = tid & 31;
    const int warp = tid >> 5;
    const int wm   = (warp & 1) * 64;
    const int wn   = (warp >> 1) * 32;
    const int n0   = blockIdx.x * 128;   // N fastest -> A-tile L2 reuse
    const int m0   = blockIdx.y * 128;
    const int sr   = tid >> 3;           // 0..31 staging row
    const int sc   = (tid & 7) * 4;      // 0..28 staging col

    float acc[4][4][4] = {};
    float4 av[4], bv[4];

    auto load_regs = [&](int kk) {
#pragma unroll
        for (int i = 0; i < 4; i++) {
            int row = sr + i * 32;
            int gm  = m0 + row;
            float4 v = make_float4(0.f, 0.f, 0.f, 0.f);
            if (gm < M) {
                const AT* p = A + (size_t)gm * lda + aoff + kk + sc;
                if constexpr (sizeof(AT) == 4) {
                    v = *(const float4*)p;
                } else {
                    uint2 u = *(const uint2*)p;
                    float2 f0 = __half22float2(*(__half2*)&u.x);
                    float2 f1 = __half22float2(*(__half2*)&u.y);
                    v = make_float4(f0.x, f0.y, f1.x, f1.y);
                }
                if (rowscale) {
                    float s = rowscale[gm];
                    v.x *= s; v.y *= s; v.z *= s; v.w *= s;
                }
                if (colscale) {
                    float4 w = *(const float4*)(colscale + kk + sc);
                    v.x *= w.x; v.y *= w.y; v.z *= w.z; v.w *= w.w;
                }
            }
            av[i] = v;
            bv[i] = *(const float4*)(W + (size_t)(n0 + row) * K + kk + sc);
        }
    };

    auto store_stage = [&](int buf) {
#pragma unroll
        for (int i = 0; i < 4; i++) {
            int row = sr + i * 32;
            __half2* pa = (__half2*)&As[buf][row * SLD + sc];
            pa[0] = __floats2half2_rn(av[i].x, av[i].y);
            pa[1] = __floats2half2_rn(av[i].z, av[i].w);
            __half2* pb = (__half2*)&Bs[buf][row * SLD + sc];
            pb[0] = __floats2half2_rn(bv[i].x, bv[i].y);
            pb[1] = __floats2half2_rn(bv[i].z, bv[i].w);
        }
    };

    auto compute = [&](int buf) {
        uint32_t baseA = smaddr(&As[buf][0]);
        uint32_t baseB = smaddr(&Bs[buf][0]);
#pragma unroll
        for (int ks = 0; ks < 2; ks++) {
            const int k0 = ks * 16;
            uint32_t a[4][4], b[4][2];
#pragma unroll
            for (int mt = 0; mt < 4; mt++) {
                int r = wm + mt * 16 + (lane & 15);
                int c = k0 + 8 * (lane >> 4);
                ldsm4(a[mt], baseA + (r * SLD + c) * 2);
            }
#pragma unroll
            for (int nt = 0; nt < 4; nt++) {
                int r = wn + nt * 8 + (lane & 7);
                int c = k0 + 8 * ((lane >> 3) & 1);
                ldsm2(b[nt], baseB + (r * SLD + c) * 2);
            }
#pragma unroll
            for (int mt = 0; mt < 4; mt++)
#pragma unroll
                for (int nt = 0; nt < 4; nt++)
                    hmma(acc[mt][nt], a[mt], b[nt]);
        }
    };

    load_regs(0);
    store_stage(0);
    __syncthreads();
    const int nk = K >> 5;
    for (int kt = 0; kt < nk; kt++) {
        int buf = kt & 1;
        if (kt + 1 < nk) load_regs((kt + 1) << 5);
        compute(buf);
        if (kt + 1 < nk) {
            store_stage(buf ^ 1);
            __syncthreads();
        }
    }

    // epilogue
    const int er = lane >> 2;
    const int ec = (lane & 3) * 2;
#pragma unroll
    for (int mt = 0; mt < 4; mt++) {
#pragma unroll
        for (int hh = 0; hh < 2; hh++) {
            int row = m0 + wm + mt * 16 + er + hh * 8;
            if (row >= M) continue;
#pragma unroll
            for (int nt = 0; nt < 4; nt++) {
                int col = wn + nt * 8 + ec;
                int gcol = n0 + col;
                float v0 = acc[mt][nt][hh * 2 + 0] + bias[gcol];
                float v1 = acc[mt][nt][hh * 2 + 1] + bias[gcol + 1];
                if (MODE == 1) { v0 = gelu_f(v0); v1 = gelu_f(v1); }
                if (MODE == 2) {
                    const float* rp = residual + (size_t)row * 512 + coff + gcol;
                    v0 += rp[0]; v1 += rp[1];
                }
                if constexpr (sizeof(OT) == 2) {
                    *(__half2*)(out + (size_t)row * ldc + coff + gcol) =
                        __floats2half2_rn(v0, v1);
                } else {
                    *(float2*)(out + (size_t)row * ldc + coff + gcol) =
                        make_float2(v0, v1);
                }
            }
        }
    }
}

// ---------------- GEMM wrappers ------------------------------------------
__global__ __launch_bounds__(256, 1) void k_gemm_qkv(
    const float* __restrict__ x, const float* __restrict__ in_w,
    const float* __restrict__ in_b, const float* __restrict__ na_w)
{
    gemm_core<0, float, float>(x, 512, 384, in_w, 128, in_b, g_rrms_a, na_w,
                               nullptr, g_qkv, 384, 0, MROWS);
}

__global__ __launch_bounds__(256, 1) void k_gemm_proj(
    const float* __restrict__ out_w, const float* __restrict__ out_b)
{
    gemm_core<0, float, __half>(g_o, 128, 0, out_w, 128, out_b, nullptr, nullptr,
                                nullptr, g_xc, 512, 384, MROWS);
}

__global__ __launch_bounds__(256, 1) void k_gemm_mlp1(
    const float* __restrict__ cm_w1, const float* __restrict__ cm_b1,
    const float* __restrict__ nf_w)
{
    gemm_core<1, __half, __half>(g_xc, 512, 0, cm_w1, 512, cm_b1, g_rrms_f, nf_w,
                                 nullptr, g_h, 1024, 0, MROWS);
}

__global__ __launch_bounds__(256, 1) void k_gemm_mlp2(
    const float* __restrict__ cm_w2, const float* __restrict__ cm_b2,
    const float* __restrict__ x, float* __restrict__ out)
{
    gemm_core<2, __half, float>(g_h, 1024, 0, cm_w2, 1024, cm_b2, nullptr, nullptr,
                                x, out, 512, 0, MROWS);
}

// ---------------- token mixer (mix over V=17, per channel d<384) ---------
__global__ __launch_bounds__(384) void k_tokenmix(
    const float* __restrict__ x,
    const float* __restrict__ w1, const float* __restrict__ b1,
    const float* __restrict__ w2, const float* __restrict__ b2)
{
    __shared__ float sw1[289], sw2[289], sb1[17], sb2[17];
    int tid = threadIdx.x;
    if (tid < 289) { sw1[tid] = w1[tid]; sw2[tid] = w2[tid]; }
    if (tid < 17)  { sb1[tid] = b1[tid]; sb2[tid] = b2[tid]; }
    __syncthreads();

    size_t base = (size_t)blockIdx.x * V_B * 512;
    int d = tid;  // 0..383
    float xv[17];
#pragma unroll
    for (int v = 0; v < 17; v++) xv[v] = x[base + (size_t)v * 512 + d];
    float h[17];
#pragma unroll
    for (int u = 0; u < 17; u++) {
        float s = sb1[u];
#pragma unroll
        for (int v = 0; v < 17; v++) s += sw1[u * 17 + v] * xv[v];
        h[u] = gelu_f(s);
    }
#pragma unroll
    for (int u = 0; u < 17; u++) {
        float s = sb2[u];
#pragma unroll
        for (int v = 0; v < 17; v++) s += sw2[u * 17 + v] * h[v];
        g_xc[base + (size_t)u * 512 + d] = __float2half(s);
    }
}

// ---------------- per-row inverse RMS ------------------------------------
__global__ __launch_bounds__(256) void k_rowrms_a(const float* __restrict__ x) {
    int row = blockIdx.x * 8 + (threadIdx.x >> 5);
    if (row >= MROWS) return;
    int lane = threadIdx.x & 31;
    const float* p = x + (size_t)row * 512 + 384;
    float ss = 0.f;
    {
        float4 v = *(const float4*)(p + lane * 4);
        ss += v.x * v.x + v.y * v.y + v.z * v.z + v.w * v.w;
    }
#pragma unroll
    for (int s = 16; s; s >>= 1) ss += __shfl_xor_sync(0xffffffffu, ss, s);
    if (lane == 0) g_rrms_a[row] = rsqrtf(ss * (1.0f / 128.0f) + 1e-6f);
}

__global__ __launch_bounds__(256) void k_rowrms_f() {
    int row = blockIdx.x * 8 + (threadIdx.x >> 5);
    if (row >= MROWS) return;
    int lane = threadIdx.x & 31;
    const __half* p = g_xc + (size_t)row * 512;
    float ss = 0.f;
#pragma unroll
    for (int i = lane * 8; i < 512; i += 256) {
        uint4 u = *(const uint4*)(p + i);
        __half2* h = (__half2*)&u;
#pragma unroll
        for (int j = 0; j < 4; j++) {
            float2 f = __half22float2(h[j]);
            ss += f.x * f.x + f.y * f.y;
        }
    }
#pragma unroll
    for (int s = 16; s; s >>= 1) ss += __shfl_xor_sync(0xffffffffu, ss, s);
    if (lane == 0) g_rrms_f[row] = rsqrtf(ss * (1.0f / 512.0f) + 1e-6f);
}

// ---------------- attention (one block per (n,t); 17x17 per head) --------
__global__ __launch_bounds__(96) void k_attn() {
    __shared__ __align__(16) float s[17 * 384];
    int b = blockIdx.x;
    const float4* g4 = (const float4*)(g_qkv + (size_t)b * 17 * 384);
    float4* s4 = (float4*)s;
    for (int i = threadIdx.x; i < 17 * 96; i += 96) s4[i] = g4[i];
    __syncthreads();

    int tid = threadIdx.x;
    if (tid < 68) {
        int q  = tid % 17;
        int hh = tid / 17;
        float qv[32];
#pragma unroll
        for (int i = 0; i < 8; i++) {
            float4 v = *(const float4*)&s[q * 384 + hh * 32 + i * 4];
            qv[i * 4] = v.x; qv[i * 4 + 1] = v.y; qv[i * 4 + 2] = v.z; qv[i * 4 + 3] = v.w;
        }
        float sc[17];
        float mx = -1e30f;
#pragma unroll
        for (int j = 0; j < 17; j++) {
            const float* kp = &s[j * 384 + 128 + hh * 32];
            float a = 0.f;
#pragma unroll
            for (int i = 0; i < 8; i++) {
                float4 v = *(const float4*)(kp + i * 4);
                a += qv[i * 4] * v.x + qv[i * 4 + 1] * v.y +
                     qv[i * 4 + 2] * v.z + qv[i * 4 + 3] * v.w;
            }
            a *= 0.17677669529663687f;  // 1/sqrt(32)
            sc[j] = a;
            mx = fmaxf(mx, a);
        }
        float sum = 0.f;
#pragma unroll
        for (int j = 0; j < 17; j++) { sc[j] = __expf(sc[j] - mx); sum += sc[j]; }
        float inv = 1.f / sum;
        float ov[32];
#pragma unroll
        for (int i = 0; i < 32; i++) ov[i] = 0.f;
#pragma unroll
        for (int j = 0; j < 17; j++) {
            float p = sc[j] * inv;
            const float* vp = &s[j * 384 + 256 + hh * 32];
#pragma unroll
            for (int i = 0; i < 8; i++) {
                float4 v = *(const float4*)(vp + i * 4);
                ov[i * 4]     += p * v.x;
                ov[i * 4 + 1] += p * v.y;
                ov[i * 4 + 2] += p * v.z;
                ov[i * 4 + 3] += p * v.w;
            }
        }
        float* op = g_o + ((size_t)b * 17 + q) * 128 + hh * 32;
#pragma unroll
        for (int i = 0; i < 8; i++)
            *(float4*)(op + i * 4) =
                make_float4(ov[i * 4], ov[i * 4 + 1], ov[i * 4 + 2], ov[i * 4 + 3]);
    }
}

// ---------------- launch --------------------------------------------------
extern "C" void kernel_launch(void* const* d_in, const int* in_sizes, int n_in,
                              void* d_out, int out_size)
{
    const float* x     = (const float*)d_in[0];
    const float* tm_w1 = (const float*)d_in[1];
    const float* tm_b1 = (const float*)d_in[2];
    const float* tm_w2 = (const float*)d_in[3];
    const float* tm_b2 = (const float*)d_in[4];
    const float* na_w  = (const float*)d_in[5];
    const float* in_w  = (const float*)d_in[6];
    const float* in_b  = (const float*)d_in[7];
    const float* out_w = (const float*)d_in[8];
    const float* out_b = (const float*)d_in[9];
    const float* nf_w  = (const float*)d_in[10];
    const float* cm_w1 = (const float*)d_in[11];
    const float* cm_b1 = (const float*)d_in[12];
    const float* cm_w2 = (const float*)d_in[13];
    const float* cm_b2 = (const float*)d_in[14];
    float* out = (float*)d_out;

    const int mt = (MROWS + 127) / 128;  // 1033 M-tiles

    k_tokenmix<<<NT_B, 384>>>(x, tm_w1, tm_b1, tm_w2, tm_b2);
    k_rowrms_a<<<MROWS / 8, 256>>>(x);
    k_gemm_qkv<<<dim3(3, mt), 256>>>(x, in_w, in_b, na_w);
    k_attn<<<NT_B, 96>>>();
    k_gemm_proj<<<dim3(1, mt), 256>>>(out_w, out_b);
    k_rowrms_f<<<MROWS / 8, 256>>>();
    k_gemm_mlp1<<<dim3(8, mt), 256>>>(cm_w1, cm_b1, nf_w);
    k_gemm_mlp2<<<dim3(4, mt), 256>>>(cm_w2, cm_b2, x, out);
}

// round 5
// speedup vs baseline: 2.7463x; 1.8223x over previous
#include <cuda_runtime.h>
#include <cuda_fp16.h>
#include <cstdint>
#include <math.h>

// Problem dims
#define N_B   32
#define T_B   243
#define V_B   17
#define NT_B  (N_B * T_B)          // 7776
#define MROWS (NT_B * V_B)         // 132192

// ---------------- scratch (static device memory; no allocations) ----------
__device__ __half g_xc [67682304];   // M*512  concat (xm_out | xa_out)
__device__ __half g_qkv[50761728];   // M*384
__device__ __half g_o  [16920576];   // M*128
__device__ __half g_h  [135364608];  // M*1024
__device__ __half h_xa [16920576];   // M*128  normalized attn input
__device__ __half h_xn [67682304];   // M*512  normalized MLP input
__device__ __half h_in_w [49152];
__device__ __half h_out_w[16384];
__device__ __half h_cm_w1[524288];
__device__ __half h_cm_w2[524288];

// ---------------- helpers -------------------------------------------------
__device__ __forceinline__ float gelu_f(float v) {
    return 0.5f * v * (1.0f + erff(v * 0.7071067811865475f));
}
__device__ __forceinline__ uint32_t smaddr(const void* p) {
    return (uint32_t)__cvta_generic_to_shared(p);
}
__device__ __forceinline__ void ldsm4(uint32_t* r, uint32_t a) {
    asm volatile("ldmatrix.sync.aligned.m8n8.x4.shared.b16 {%0,%1,%2,%3}, [%4];"
        : "=r"(r[0]), "=r"(r[1]), "=r"(r[2]), "=r"(r[3]) : "r"(a));
}
__device__ __forceinline__ void ldsm2(uint32_t* r, uint32_t a) {
    asm volatile("ldmatrix.sync.aligned.m8n8.x2.shared.b16 {%0,%1}, [%2];"
        : "=r"(r[0]), "=r"(r[1]) : "r"(a));
}
__device__ __forceinline__ void hmma(float* d, const uint32_t* a, const uint32_t* b) {
    asm volatile(
        "mma.sync.aligned.m16n8k16.row.col.f32.f16.f16.f32 "
        "{%0,%1,%2,%3},{%4,%5,%6,%7},{%8,%9},{%0,%1,%2,%3};"
        : "+f"(d[0]), "+f"(d[1]), "+f"(d[2]), "+f"(d[3])
        : "r"(a[0]), "r"(a[1]), "r"(a[2]), "r"(a[3]), "r"(b[0]), "r"(b[1]));
}
__device__ __forceinline__ void cp16(uint32_t dst, const void* src, bool pred) {
    int sz = pred ? 16 : 0;
    asm volatile("cp.async.cg.shared.global [%0], [%1], 16, %2;\n"
        :: "r"(dst), "l"(src), "r"(sz));
}
__device__ __forceinline__ void cp_commit() {
    asm volatile("cp.async.commit_group;\n" ::: "memory");
}
template <int NN>
__device__ __forceinline__ void cp_wait() {
    asm volatile("cp.async.wait_group %0;\n" :: "n"(NN) : "memory");
}

// swizzled offset inside a 128x32 fp16 stage tile (conflict-free for
// cp.async 16B stores and ldmatrix 8x16B reads)
__device__ __forceinline__ int sw_off(int row, int col) {
    return row * 32 + ((((col >> 3) ^ (row >> 1)) & 3) << 3) + (col & 7);
}

// ---------------- fp16 GEMM: out = act(A * W^T + bias) --------------------
// A: M x K fp16 (lda), W: N x K fp16. 128x128x32 tiles, 3-stage cp.async.
// MODE: 0 = bias, 1 = bias+gelu, 2 = bias+residual(fp32 x, stride 512)
#define STAGES 3

template <int MODE, typename OT>
__device__ __forceinline__ void gemm_core(
    const __half* __restrict__ A, int lda,
    const __half* __restrict__ W, int K,
    const float* __restrict__ bias,
    const float* __restrict__ residual,
    OT* __restrict__ out, int ldc, int coff,
    int M)
{
    __shared__ __half As[STAGES][128 * 32];
    __shared__ __half Bs[STAGES][128 * 32];

    const int tid  = threadIdx.x;
    const int lane = tid & 31;
    const int warp = tid >> 5;
    const int wm   = (warp & 1) * 64;
    const int wn   = (warp >> 1) * 32;
    const int n0   = blockIdx.x * 128;   // N fastest -> A-tile L2 reuse
    const int m0   = blockIdx.y * 128;

    // staging map: 2 chunks each for A and B per thread per stage
    const int r0 = tid >> 2;             // chunk rows (c = tid, tid+256)
    const int g0 = tid & 3;
    const int r1 = (tid + 256) >> 2;
    const int g1 = g0;                   // (tid+256)&3 == tid&3

    float acc[4][4][4] = {};

    auto issue = [&](int buf, int kk) {
        uint32_t da = smaddr(&As[buf][0]);
        uint32_t db = smaddr(&Bs[buf][0]);
        const __half* ap = A + (size_t)(m0 + r0) * lda + kk + g0 * 8;
        cp16(da + sw_off(r0, g0 * 8) * 2, ap, (m0 + r0) < M);
        ap = A + (size_t)(m0 + r1) * lda + kk + g1 * 8;
        cp16(da + sw_off(r1, g1 * 8) * 2, ap, (m0 + r1) < M);
        const __half* bp = W + (size_t)(n0 + r0) * K + kk + g0 * 8;
        cp16(db + sw_off(r0, g0 * 8) * 2, bp, true);
        bp = W + (size_t)(n0 + r1) * K + kk + g1 * 8;
        cp16(db + sw_off(r1, g1 * 8) * 2, bp, true);
    };

    auto compute = [&](int buf) {
        uint32_t baseA = smaddr(&As[buf][0]);
        uint32_t baseB = smaddr(&Bs[buf][0]);
#pragma unroll
        for (int ks = 0; ks < 2; ks++) {
            const int k0 = ks * 16;
            uint32_t a[4][4], b[4][2];
#pragma unroll
            for (int mt = 0; mt < 4; mt++) {
                int r = wm + mt * 16 + (lane & 15);
                int c = k0 + 8 * (lane >> 4);
                ldsm4(a[mt], baseA + sw_off(r, c) * 2);
            }
#pragma unroll
            for (int nt = 0; nt < 4; nt++) {
                int r = wn + nt * 8 + (lane & 7);
                int c = k0 + 8 * ((lane >> 3) & 1);
                ldsm2(b[nt], baseB + sw_off(r, c) * 2);
            }
#pragma unroll
            for (int mt = 0; mt < 4; mt++)
#pragma unroll
                for (int nt = 0; nt < 4; nt++)
                    hmma(acc[mt][nt], a[mt], b[nt]);
        }
    };

    const int nk = K >> 5;
    int fetch = 0;
#pragma unroll
    for (int s = 0; s < STAGES - 1; s++) {
        if (fetch < nk) issue(fetch % STAGES, fetch << 5);
        cp_commit();
        fetch++;
    }
    for (int kt = 0; kt < nk; kt++) {
        cp_wait<STAGES - 2>();
        __syncthreads();
        compute(kt % STAGES);
        __syncthreads();
        if (fetch < nk) issue(fetch % STAGES, fetch << 5);
        cp_commit();
        fetch++;
    }

    // epilogue
    const int er = lane >> 2;
    const int ec = (lane & 3) * 2;
#pragma unroll
    for (int mt = 0; mt < 4; mt++) {
#pragma unroll
        for (int hh = 0; hh < 2; hh++) {
            int row = m0 + wm + mt * 16 + er + hh * 8;
            if (row >= M) continue;
#pragma unroll
            for (int nt = 0; nt < 4; nt++) {
                int col  = wn + nt * 8 + ec;
                int gcol = n0 + col;
                float v0 = acc[mt][nt][hh * 2 + 0] + bias[gcol];
                float v1 = acc[mt][nt][hh * 2 + 1] + bias[gcol + 1];
                if (MODE == 1) { v0 = gelu_f(v0); v1 = gelu_f(v1); }
                if (MODE == 2) {
                    const float* rp = residual + (size_t)row * 512 + coff + gcol;
                    v0 += rp[0]; v1 += rp[1];
                }
                if constexpr (sizeof(OT) == 2) {
                    *(__half2*)(out + (size_t)row * ldc + coff + gcol) =
                        __floats2half2_rn(v0, v1);
                } else {
                    *(float2*)(out + (size_t)row * ldc + coff + gcol) =
                        make_float2(v0, v1);
                }
            }
        }
    }
}

// ---------------- GEMM wrappers ------------------------------------------
__global__ __launch_bounds__(256, 2) void k_gemm_qkv(const float* __restrict__ in_b) {
    gemm_core<0, __half>(h_xa, 128, h_in_w, 128, in_b, nullptr,
                         g_qkv, 384, 0, MROWS);
}
__global__ __launch_bounds__(256, 2) void k_gemm_proj(const float* __restrict__ out_b) {
    gemm_core<0, __half>(g_o, 128, h_out_w, 128, out_b, nullptr,
                         g_xc, 512, 384, MROWS);
}
__global__ __launch_bounds__(256, 2) void k_gemm_mlp1(const float* __restrict__ cm_b1) {
    gemm_core<1, __half>(h_xn, 512, h_cm_w1, 512, cm_b1, nullptr,
                         g_h, 1024, 0, MROWS);
}
__global__ __launch_bounds__(256, 2) void k_gemm_mlp2(
    const float* __restrict__ cm_b2, const float* __restrict__ x,
    float* __restrict__ out)
{
    gemm_core<2, float>(g_h, 1024, h_cm_w2, 1024, cm_b2, x,
                        out, 512, 0, MROWS);
}

// ---------------- weight conversion fp32 -> fp16 --------------------------
__global__ __launch_bounds__(256) void k_cvt_w(
    const float* __restrict__ in_w, const float* __restrict__ out_w,
    const float* __restrict__ cm_w1, const float* __restrict__ cm_w2)
{
    int i = blockIdx.x * 256 + threadIdx.x;
    if (i < 49152) h_in_w[i] = __float2half(in_w[i]);
    if (i < 16384) h_out_w[i] = __float2half(out_w[i]);
    if (i < 524288) {
        h_cm_w1[i] = __float2half(cm_w1[i]);
        h_cm_w2[i] = __float2half(cm_w2[i]);
    }
}

// ---------------- token mixer (mix over V=17, channels d<384) -------------
__global__ __launch_bounds__(384) void k_tokenmix(
    const float* __restrict__ x,
    const float* __restrict__ w1, const float* __restrict__ b1,
    const float* __restrict__ w2, const float* __restrict__ b2)
{
    __shared__ float sw1[289], sw2[289], sb1[17], sb2[17];
    int tid = threadIdx.x;
    if (tid < 289) { sw1[tid] = w1[tid]; sw2[tid] = w2[tid]; }
    if (tid < 17)  { sb1[tid] = b1[tid]; sb2[tid] = b2[tid]; }
    __syncthreads();

    size_t base = (size_t)blockIdx.x * V_B * 512;
    int d = tid;  // 0..383
    float xv[17];
#pragma unroll
    for (int v = 0; v < 17; v++) xv[v] = x[base + (size_t)v * 512 + d];
    float h[17];
#pragma unroll
    for (int u = 0; u < 17; u++) {
        float s = sb1[u];
#pragma unroll
        for (int v = 0; v < 17; v++) s += sw1[u * 17 + v] * xv[v];
        h[u] = gelu_f(s);
    }
#pragma unroll
    for (int u = 0; u < 17; u++) {
        float s = sb2[u];
#pragma unroll
        for (int v = 0; v < 17; v++) s += sw2[u * 17 + v] * h[v];
        g_xc[base + (size_t)u * 512 + d] = __float2half(s);
    }
}

// ---------------- RMSNorm prep: write normalized fp16 A -------------------
__global__ __launch_bounds__(256) void k_prep_a(
    const float* __restrict__ x, const float* __restrict__ na_w)
{
    int row = blockIdx.x * 8 + (threadIdx.x >> 5);
    if (row >= MROWS) return;
    int lane = threadIdx.x & 31;
    const float* p = x + (size_t)row * 512 + 384;
    float4 v = *(const float4*)(p + lane * 4);
    float ss = v.x * v.x + v.y * v.y + v.z * v.z + v.w * v.w;
#pragma unroll
    for (int s = 16; s; s >>= 1) ss += __shfl_xor_sync(0xffffffffu, ss, s);
    float r = rsqrtf(ss * (1.0f / 128.0f) + 1e-6f);
    float4 w = *(const float4*)(na_w + lane * 4);
    __half2* o = (__half2*)(h_xa + (size_t)row * 128 + lane * 4);
    o[0] = __floats2half2_rn(v.x * r * w.x, v.y * r * w.y);
    o[1] = __floats2half2_rn(v.z * r * w.z, v.w * r * w.w);
}

__global__ __launch_bounds__(256) void k_prep_f(const float* __restrict__ nf_w) {
    int row = blockIdx.x * 8 + (threadIdx.x >> 5);
    if (row >= MROWS) return;
    int lane = threadIdx.x & 31;
    const __half* p = g_xc + (size_t)row * 512;
    float vals[16];
    float ss = 0.f;
#pragma unroll
    for (int c = 0; c < 2; c++) {
        uint4 u = *(const uint4*)(p + lane * 8 + c * 256);
        __half2* h = (__half2*)&u;
#pragma unroll
        for (int j = 0; j < 4; j++) {
            float2 f = __half22float2(h[j]);
            vals[c * 8 + j * 2] = f.x; vals[c * 8 + j * 2 + 1] = f.y;
            ss += f.x * f.x + f.y * f.y;
        }
    }
#pragma unroll
    for (int s = 16; s; s >>= 1) ss += __shfl_xor_sync(0xffffffffu, ss, s);
    float r = rsqrtf(ss * (1.0f / 512.0f) + 1e-6f);
    __half* o = h_xn + (size_t)row * 512;
#pragma unroll
    for (int c = 0; c < 2; c++) {
        int base = lane * 8 + c * 256;
        __half2 hh[4];
#pragma unroll
        for (int j = 0; j < 4; j++) {
            float w0 = nf_w[base + j * 2], w1 = nf_w[base + j * 2 + 1];
            hh[j] = __floats2half2_rn(vals[c * 8 + j * 2] * r * w0,
                                      vals[c * 8 + j * 2 + 1] * r * w1);
        }
        *(uint4*)(o + base) = *(uint4*)hh;
    }
}

// ---------------- attention (one block per (n,t); 17x17 per head) ---------
__global__ __launch_bounds__(96) void k_attn() {
    __shared__ __align__(16) float s[17 * 384];
    int b = blockIdx.x;
    const uint4* g4 = (const uint4*)(g_qkv + (size_t)b * 17 * 384);
    for (int i = threadIdx.x; i < 17 * 48; i += 96) {
        uint4 u = g4[i];
        __half2* h = (__half2*)&u;
        float* dst = &s[i * 8];
#pragma unroll
        for (int j = 0; j < 4; j++) {
            float2 f = __half22float2(h[j]);
            dst[j * 2] = f.x; dst[j * 2 + 1] = f.y;
        }
    }
    __syncthreads();

    int tid = threadIdx.x;
    if (tid < 68) {
        int q  = tid % 17;
        int hh = tid / 17;
        float qv[32];
#pragma unroll
        for (int i = 0; i < 8; i++) {
            float4 v = *(const float4*)&s[q * 384 + hh * 32 + i * 4];
            qv[i * 4] = v.x; qv[i * 4 + 1] = v.y; qv[i * 4 + 2] = v.z; qv[i * 4 + 3] = v.w;
        }
        float sc[17];
        float mx = -1e30f;
#pragma unroll
        for (int j = 0; j < 17; j++) {
            const float* kp = &s[j * 384 + 128 + hh * 32];
            float a = 0.f;
#pragma unroll
            for (int i = 0; i < 8; i++) {
                float4 v = *(const float4*)(kp + i * 4);
                a += qv[i * 4] * v.x + qv[i * 4 + 1] * v.y +
                     qv[i * 4 + 2] * v.z + qv[i * 4 + 3] * v.w;
            }
            a *= 0.17677669529663687f;
            sc[j] = a;
            mx = fmaxf(mx, a);
        }
        float sum = 0.f;
#pragma unroll
        for (int j = 0; j < 17; j++) { sc[j] = __expf(sc[j] - mx); sum += sc[j]; }
        float inv = 1.f / sum;
        float ov[32];
#pragma unroll
        for (int i = 0; i < 32; i++) ov[i] = 0.f;
#pragma unroll
        for (int j = 0; j < 17; j++) {
            float p = sc[j] * inv;
            const float* vp = &s[j * 384 + 256 + hh * 32];
#pragma unroll
            for (int i = 0; i < 8; i++) {
                float4 v = *(const float4*)(vp + i * 4);
                ov[i * 4]     += p * v.x;
                ov[i * 4 + 1] += p * v.y;
                ov[i * 4 + 2] += p * v.z;
                ov[i * 4 + 3] += p * v.w;
            }
        }
        __half* op = g_o + ((size_t)b * 17 + q) * 128 + hh * 32;
#pragma unroll
        for (int i = 0; i < 8; i++)
            *(__half2*)(op + i * 4) = __floats2half2_rn(ov[i * 4], ov[i * 4 + 1]),
            *(__half2*)(op + i * 4 + 2) = __floats2half2_rn(ov[i * 4 + 2], ov[i * 4 + 3]);
    }
}

// ---------------- launch --------------------------------------------------
extern "C" void kernel_launch(void* const* d_in, const int* in_sizes, int n_in,
                              void* d_out, int out_size)
{
    const float* x     = (const float*)d_in[0];
    const float* tm_w1 = (const float*)d_in[1];
    const float* tm_b1 = (const float*)d_in[2];
    const float* tm_w2 = (const float*)d_in[3];
    const float* tm_b2 = (const float*)d_in[4];
    const float* na_w  = (const float*)d_in[5];
    const float* in_w  = (const float*)d_in[6];
    const float* in_b  = (const float*)d_in[7];
    const float* out_w = (const float*)d_in[8];
    const float* out_b = (const float*)d_in[9];
    const float* nf_w  = (const float*)d_in[10];
    const float* cm_w1 = (const float*)d_in[11];
    const float* cm_b1 = (const float*)d_in[12];
    const float* cm_w2 = (const float*)d_in[13];
    const float* cm_b2 = (const float*)d_in[14];
    float* out = (float*)d_out;

    const int mt = (MROWS + 127) / 128;  // 1033 M-tiles

    k_cvt_w<<<2048, 256>>>(in_w, out_w, cm_w1, cm_w2);
    k_tokenmix<<<NT_B, 384>>>(x, tm_w1, tm_b1, tm_w2, tm_b2);
    k_prep_a<<<(MROWS + 7) / 8, 256>>>(x, na_w);
    k_gemm_qkv<<<dim3(3, mt), 256>>>(in_b);
    k_attn<<<NT_B, 96>>>();
    k_gemm_proj<<<dim3(1, mt), 256>>>(out_b);
    k_prep_f<<<(MROWS + 7) / 8, 256>>>(nf_w);
    k_gemm_mlp1<<<dim3(8, mt), 256>>>(cm_b1);
    k_gemm_mlp2<<<dim3(4, mt), 256>>>(cm_b2, x, out);
}